// round 2
// baseline (speedup 1.0000x reference)
#include <cuda_runtime.h>
#include <cuda_bf16.h>

// FCNNSlopeValuationFunction: B=4M rows.
// z_1: [B,16] f32  (cols: 0=line, 1=lx, 2=ly, 3=rx, 4=ry)
// dir: [B,8]  f32
// out: [B]    f32
//
// out[i] = (z[i,0]!=0) ? dir[i, zone(z[i])] : 0
// zone: phi = deg(atan2(-(ry-ly), rx-lx)); phi<0 -> 360+phi;
//       t = (90 + trunc(phi)) % 360; zone = ((t+11)/22) % 8

__global__ void __launch_bounds__(256)
slope_zone_kernel(const float* __restrict__ z,
                  const float* __restrict__ dir,
                  float* __restrict__ out,
                  int B)
{
    const int i = blockIdx.x * blockDim.x + threadIdx.x;
    if (i >= B) return;

    // --- Issue ALL loads up front (3 independent LDGs, no dependent chain) ---
    // z row: cols 0..4 live in the row's first 32B sector -> float4 + scalar.
    const float4 z0 = __ldg(reinterpret_cast<const float4*>(z) + (size_t)i * 4); // cols 0..3
    const float  ry = __ldg(z + (size_t)i * 16 + 4);                             // col 4
    // dir row: 8 floats = exactly one 32B sector. Loading the whole row costs
    // the same DRAM traffic as a gathered scalar, but removes the dependent load.
    const float4 dlo = __ldg(reinterpret_cast<const float4*>(dir) + (size_t)i * 2);
    const float4 dhi = __ldg(reinterpret_cast<const float4*>(dir) + (size_t)i * 2 + 1);

    const float line = z0.x;
    const float dx = z0.w - z0.y;        // rx - lx
    const float dy = -(ry - z0.z);       // -(ry - ly)

    // degrees(atan2), mapped to [0, 360)
    float phi = atan2f(dy, dx) * 57.29577951308232f;
    if (phi < 0.0f) phi = 360.0f + phi;

    // int32 cast truncates; phi >= 0 so truncation == floor
    const int ip = (int)phi;
    const int t  = (90 + ip) % 360;          // 0..359
    const int zone = ((t + 11) / 22) & 7;    // area_angle=22, half=11; %8

    // Branchless 3-level select of dir[zone] (avoids local-memory dynamic index)
    const bool b0 = (zone & 1) != 0;
    const bool b1 = (zone & 2) != 0;
    const bool b2 = (zone & 4) != 0;
    const float s00 = b0 ? dlo.y : dlo.x;   // zone 1 : 0
    const float s01 = b0 ? dlo.w : dlo.z;   // zone 3 : 2
    const float s10 = b0 ? dhi.y : dhi.x;   // zone 5 : 4
    const float s11 = b0 ? dhi.w : dhi.z;   // zone 7 : 6
    const float sl  = b1 ? s01 : s00;
    const float sh  = b1 ? s11 : s10;
    const float picked = b2 ? sh : sl;

    out[i] = (line != 0.0f) ? picked : 0.0f;
}

extern "C" void kernel_launch(void* const* d_in, const int* in_sizes, int n_in,
                              void* d_out, int out_size)
{
    const float* z   = (const float*)d_in[0];   // [B,16]
    const float* dir = (const float*)d_in[1];   // [B,8]
    float* out = (float*)d_out;

    const int B = in_sizes[0] / 16;

    const int threads = 256;
    const int blocks  = (B + threads - 1) / threads;
    slope_zone_kernel<<<blocks, threads>>>(z, dir, out, B);
}

// round 10
// speedup vs baseline: 1.0036x; 1.0036x over previous
#include <cuda_runtime.h>
#include <cuda_bf16.h>

// FCNNSlopeValuationFunction: B=4M rows.
// z_1: [B,16] f32  (cols: 0=line, 1=lx, 2=ly, 3=rx, 4=ry)
// dir: [B,8]  f32
// out: [B]    f32
//
// out[i] = (z[i,0]!=0) ? dir[i, zone(z[i])] : 0
// zone: phi = deg(atan2(-(ry-ly), rx-lx)); phi<0 -> 360+phi;
//       t = (90 + trunc(phi)) % 360; zone = ((t+11)/22) % 8
//
// Memory model (measured R2): DRAM granularity 64B -> floor = 64B/z-row +
// 32B/dir-row + 4B/out = 400MB total. This kernel targets utilization, not
// bytes: 2 rows/thread, 8 front-batched independent LDGs, float2 store.

__device__ __forceinline__ float zone_pick(float line, float lx, float ly,
                                           float rx, float ry,
                                           const float4& dlo, const float4& dhi)
{
    const float dx = rx - lx;
    const float dy = -(ry - ly);

    float phi = atan2f(dy, dx) * 57.29577951308232f;
    if (phi < 0.0f) phi = 360.0f + phi;

    const int ip   = (int)phi;               // trunc == floor (phi >= 0)
    const int t    = (90 + ip) % 360;        // 0..359
    const int zone = ((t + 11) / 22) & 7;    // area_angle=22, half=11; %8

    // branchless select of dir[zone]
    const bool b0 = (zone & 1) != 0;
    const bool b1 = (zone & 2) != 0;
    const bool b2 = (zone & 4) != 0;
    const float s00 = b0 ? dlo.y : dlo.x;
    const float s01 = b0 ? dlo.w : dlo.z;
    const float s10 = b0 ? dhi.y : dhi.x;
    const float s11 = b0 ? dhi.w : dhi.z;
    const float sl  = b1 ? s01 : s00;
    const float sh  = b1 ? s11 : s10;
    const float picked = b2 ? sh : sl;

    return (line != 0.0f) ? picked : 0.0f;
}

__global__ void __launch_bounds__(256)
slope_zone_kernel2(const float* __restrict__ z,
                   const float* __restrict__ dir,
                   float* __restrict__ out,
                   int Bpair)   // number of row-PAIRS
{
    const int i = blockIdx.x * blockDim.x + threadIdx.x;
    if (i >= Bpair) return;

    const size_t r0 = (size_t)i * 2;   // first row of this thread's pair

    // ---- front-batch all 8 independent loads ----
    // z rows 2i and 2i+1 share one 128B line; cols 0..4 of each row.
    const float4 za  = __ldg(reinterpret_cast<const float4*>(z) + r0 * 4);       // row 2i,  cols 0..3
    const float  rya = __ldg(z + r0 * 16 + 4);                                   // row 2i,  col 4
    const float4 zb  = __ldg(reinterpret_cast<const float4*>(z) + r0 * 4 + 4);   // row 2i+1, cols 0..3
    const float  ryb = __ldg(z + r0 * 16 + 20);                                  // row 2i+1, col 4
    // dir rows 2i and 2i+1 = one contiguous 64B line per thread.
    const float4 da0 = __ldg(reinterpret_cast<const float4*>(dir) + r0 * 2);
    const float4 da1 = __ldg(reinterpret_cast<const float4*>(dir) + r0 * 2 + 1);
    const float4 db0 = __ldg(reinterpret_cast<const float4*>(dir) + r0 * 2 + 2);
    const float4 db1 = __ldg(reinterpret_cast<const float4*>(dir) + r0 * 2 + 3);

    float2 res;
    res.x = zone_pick(za.x, za.y, za.z, za.w, rya, da0, da1);
    res.y = zone_pick(zb.x, zb.y, zb.z, zb.w, ryb, db0, db1);

    reinterpret_cast<float2*>(out)[i] = res;   // coalesced 8B store
}

extern "C" void kernel_launch(void* const* d_in, const int* in_sizes, int n_in,
                              void* d_out, int out_size)
{
    const float* z   = (const float*)d_in[0];   // [B,16]
    const float* dir = (const float*)d_in[1];   // [B,8]
    float* out = (float*)d_out;

    const int B = in_sizes[0] / 16;             // 4,000,000 (even)
    const int Bpair = B >> 1;

    const int threads = 256;
    const int blocks  = (Bpair + threads - 1) / threads;
    slope_zone_kernel2<<<blocks, threads>>>(z, dir, out, Bpair);
}

// round 12
// speedup vs baseline: 1.0162x; 1.0126x over previous
#include <cuda_runtime.h>
#include <cuda_bf16.h>

// FCNNSlopeValuationFunction: B=4M rows.
// z_1: [B,16] f32  (cols: 0=line, 1=lx, 2=ly, 3=rx, 4=ry)
// dir: [B,8]  f32
// out: [B]    f32
//
// out[i] = (z[i,0]!=0) ? dir[i, zone(z[i])] : 0
//
// Measured: traffic is at the 64B-granularity byte floor (~400MB); R2 1-row
// kernel hit 6758 GB/s (85.3% DRAM). R10 2-row variant REGRESSED residency
// (82.5%) -> bandwidth-bound, not latency-bound. This round: identical R2
// structure, ONLY change = streaming cache policy (__ldcs/__stcs) to cut L2
// thrash between the three 128-400MB streams.

__global__ void __launch_bounds__(256)
slope_zone_kernel(const float* __restrict__ z,
                  const float* __restrict__ dir,
                  float* __restrict__ out,
                  int B)
{
    const int i = blockIdx.x * blockDim.x + threadIdx.x;
    if (i >= B) return;

    // z row: cols 0..4 live in the row's first 32B sector -> float4 + scalar.
    // Streaming (evict-first) loads: data is touched exactly once.
    const float4 z0 = __ldcs(reinterpret_cast<const float4*>(z) + (size_t)i * 4); // cols 0..3
    const float  ry = __ldcs(z + (size_t)i * 16 + 4);                             // col 4

    const float line = z0.x;
    const float dx = z0.w - z0.y;        // rx - lx
    const float dy = -(ry - z0.z);       // -(ry - ly)

    // degrees(atan2), mapped to [0, 360)
    float phi = atan2f(dy, dx) * 57.29577951308232f;
    if (phi < 0.0f) phi = 360.0f + phi;

    // int32 cast truncates; phi >= 0 so truncation == floor
    const int ip   = (int)phi;
    const int t    = (90 + ip) % 360;        // 0..359
    const int zone = ((t + 11) / 22) & 7;    // area_angle=22, half=11; %8

    // gather one float from this row's dir (one 32B sector per row either way)
    const float picked = __ldcs(dir + (size_t)i * 8 + zone);

    __stcs(out + i, (line != 0.0f) ? picked : 0.0f);
}

extern "C" void kernel_launch(void* const* d_in, const int* in_sizes, int n_in,
                              void* d_out, int out_size)
{
    const float* z   = (const float*)d_in[0];   // [B,16]
    const float* dir = (const float*)d_in[1];   // [B,8]
    float* out = (float*)d_out;

    const int B = in_sizes[0] / 16;

    const int threads = 256;
    const int blocks  = (B + threads - 1) / threads;
    slope_zone_kernel<<<blocks, threads>>>(z, dir, out, B);
}